// round 14
// baseline (speedup 1.0000x reference)
#include <cuda_runtime.h>
#include <cstdint>

#define CDIM  768
#define CDIM4 192           // CDIM/4
#define NTHREADS 256
#define NBLOCKS  302        // 152 SMs * 2 slots - 2 reserved for ceFlag
#define TM 128
#define TN 128
#define TK 32
#define KTILES (CDIM / TK)  // 24
#define JTILES (CDIM / TN)  // 6
#define QOFF 4096           // scratch stride (max B = 4096)
#define TMP (TM + 4)        // padded smem row
#define BUFB 49152          // 48 KB TMA staging buffer
#define SMEM_HDR 1024
#define SMEM_TOTAL (SMEM_HDR + 2 * BUFB)   // 99328 B dynamic smem

// quadratic-form scratch: [0,B) text, [QOFF,QOFF+B) graph. Zero at entry:
// zero-initialized at load; re-zeroed by finalize items each replay.
__device__ float g_quad[2 * QOFF];
__device__ unsigned g_ctr;              // work-queue head
__device__ unsigned g_passed;           // blocks past all pre-finalize work
__device__ unsigned g_exit;             // exited blocks
__device__ unsigned g_ceDone;           // set by ceFlag after CE memcpys done

// user_index may be int64 (declared) or int32 (JAX x64-off default).
__device__ __forceinline__ int detect_is64(const void* uptr, int B, long long nrows) {
    if (B < 2) return 1;
    long long v = ((const long long*)uptr)[B / 2 - 1];
    return (v >= 0 && v < nrows) ? 1 : 0;
}
__device__ __forceinline__ long long load_idx(const void* uptr, int i, int is64) {
    if (is64) return ((const long long*)uptr)[i];
    return (long long)((const int*)uptr)[i];
}

// ---- packed fp32x2 helpers (SASS FFMA2; ptxas never auto-fuses) ----
__device__ __forceinline__ unsigned long long dup2(float a) {
    unsigned long long d; unsigned ai = __float_as_uint(a);
    asm("mov.b64 %0, {%1, %1};" : "=l"(d) : "r"(ai));
    return d;
}
__device__ __forceinline__ void fma2(unsigned long long& acc,
                                     unsigned long long a, unsigned long long b) {
    asm("fma.rn.f32x2 %0, %1, %2, %0;" : "+l"(acc) : "l"(a), "l"(b));
}
__device__ __forceinline__ float2 unpack2(unsigned long long v) {
    float2 r;
    asm("mov.b64 {%0, %1}, %2;" : "=f"(r.x), "=f"(r.y) : "l"(v));
    return r;
}

// ---- TMA bulk + mbarrier helpers ----
__device__ __forceinline__ uint32_t smem_u32(const void* p) {
    uint32_t a;
    asm("{ .reg .u64 t; cvta.to.shared.u64 t, %1; cvt.u32.u64 %0, t; }"
        : "=r"(a) : "l"(p));
    return a;
}
__device__ __forceinline__ void mbar_init(uint32_t mb, uint32_t cnt) {
    asm volatile("mbarrier.init.shared.b64 [%0], %1;" :: "r"(mb), "r"(cnt) : "memory");
}
__device__ __forceinline__ void mbar_expect_tx(uint32_t mb, uint32_t bytes) {
    asm volatile("mbarrier.arrive.expect_tx.shared.b64 _, [%0], %1;"
                 :: "r"(mb), "r"(bytes) : "memory");
}
__device__ __forceinline__ void mbar_wait(uint32_t mb, uint32_t parity) {
    asm volatile(
        "{\n\t"
        ".reg .pred P1;\n\t"
        "WAIT_LOOP_%=:\n\t"
        "mbarrier.try_wait.parity.acquire.cta.shared::cta.b64 P1, [%0], %1, 0x989680;\n\t"
        "@P1 bra.uni WAIT_DONE_%=;\n\t"
        "bra.uni WAIT_LOOP_%=;\n\t"
        "WAIT_DONE_%=:\n\t"
        "}"
        :: "r"(mb), "r"(parity) : "memory");
}
__device__ __forceinline__ void bulk_g2s(uint32_t dst, const void* src,
                                         uint32_t bytes, uint32_t mb) {
    asm volatile(
        "cp.async.bulk.shared::cta.global.mbarrier::complete_tx::bytes "
        "[%0], [%1], %2, [%3];"
        :: "r"(dst), "l"(src), "r"(bytes), "r"(mb) : "memory");
}
__device__ __forceinline__ void bulk_s2g(void* dst, uint32_t src, uint32_t bytes) {
    asm volatile(
        "cp.async.bulk.global.shared::cta.bulk_group [%0], [%1], %2;"
        :: "l"(dst), "r"(src), "r"(bytes) : "memory");
}
#define BULK_COMMIT()  asm volatile("cp.async.bulk.commit_group;" ::: "memory")
#define BULK_WAIT(n)   asm volatile("cp.async.bulk.wait_group " #n ";" ::: "memory")
#define FENCE_ASYNC()  asm volatile("fence.proxy.async.shared::cta;" ::: "memory")

// ---------------------------------------------------------------------------
// ceFlag: 1-thread kernel on the side stream, launched after both CE memcpys
// complete (stream order). Runs in one of the 2 reserved SM slots while mega
// is resident. Finalize items spin on g_ceDone before overwriting outU rows.
// ---------------------------------------------------------------------------
__global__ void ceFlag() {
    __threadfence();
    g_ceDone = 1u;
}

// ---------------------------------------------------------------------------
// Mega kernel. Queue items:
//   [0, NITEMS): g=item/P; GEMM tile if item%P==0 && g<NG; else a 48 KB TMA
//                bulk copy chunk of text -> outT (double-buffered in smem).
//   [NITEMS, TOTAL): finalize rows — wait g_passed == gridDim.x AND g_ceDone
//                (CE memcpys of user -> outU are retired), then write blended
//                text s=0 slices to outT and blended user rows DIRECTLY to outU.
// ---------------------------------------------------------------------------
__global__ void __launch_bounds__(NTHREADS, 2)
mega(const float* __restrict__ text,
     const float* __restrict__ user,
     const void*  __restrict__ uidx,
     const float* __restrict__ Wt,
     const float* __restrict__ bt,
     const float* __restrict__ Wg,
     const float* __restrict__ bg,
     float* __restrict__ outAll,           // outT (text_n) then outU (user_n)
     int B, long long SC, long long text_n, long long user_rows,
     unsigned NG, unsigned P, unsigned NITEMS, unsigned TOTAL)
{
    extern __shared__ char smdyn[];
    unsigned* s_item = (unsigned*)smdyn;
    const uint32_t mbarBase = smem_u32(smdyn + 64);
    const uint32_t bufBase  = smem_u32(smdyn + SMEM_HDR);
    float (*As)[TMP] = (float(*)[TMP])(smdyn + SMEM_HDR);
    float (*Bs)[TMP] = (float(*)[TMP])(smdyn + SMEM_HDR + TK * TMP * 4);

    const int tid  = threadIdx.x;
    const int warp = tid >> 5;
    const int lane = tid & 31;
    const int tx   = tid & 15;    // j-fragment index
    const int ty   = tid >> 4;    // row-fragment index

    const size_t TB = (size_t)text_n * 4;   // text bytes
    const unsigned perM = NG >> 1;

    if (tid == 0) {
        mbar_init(mbarBase + 0, 1);
        mbar_init(mbarBase + 8, 1);
        asm volatile("fence.mbarrier_init.release.cluster;" ::: "memory");
        *s_item = atomicAdd(&g_ctr, 1u);
    }
    __syncthreads();
    unsigned item = *s_item;
    bool passed = false;
    unsigned ph0 = 0, ph1 = 0;    // mbarrier phases (tid0 only)
    int cpyCnt = 0;               // per-block copy-slot alternation

    const int is64 = detect_is64(uidx, B, user_rows);

    for (;;) {
        if (!passed && item >= NITEMS) {
            if (tid == 0) {
                BULK_WAIT(0);                // all async stores retired
                __threadfence();
                atomicAdd(&g_passed, 1u);
            }
            passed = true;
        }
        if (item >= TOTAL) break;

        const unsigned g = item / P;
        const bool isGemm = (item < NITEMS) && (item - g * P == 0u) && (g < NG);

        if (isGemm) {
            // ================= GEMM bilinear-form tile =================
            if (tid == 0) BULK_WAIT(0);      // smem buffers free for reuse
            __syncthreads();

            const int isG = (g >= perM) ? 1 : 0;
            const int qq  = isG ? (int)(g - perM) : (int)g;
            const int mt  = qq / JTILES;
            const int jt  = qq % JTILES;
            const int row0 = mt * TM;
            const int j0   = jt * TN;
            const float* __restrict__ Wm = isG ? Wg : Wt;

            unsigned long long acc[8][4];
            #pragma unroll
            for (int i = 0; i < 8; i++)
                #pragma unroll
                for (int j = 0; j < 4; j++) acc[i][j] = 0ull;

            for (int kt = 0; kt < KTILES; kt++) {
                const int kb4 = kt * (TK / 4);
                __syncthreads();
                #pragma unroll
                for (int it = 0; it < 4; it++) {
                    const int f  = it * NTHREADS + tid;
                    const int r  = f >> 3;
                    const int qd = f & 7;
                    int rr = row0 + r; if (rr >= B) rr = B - 1;
                    const float* arow;
                    if (isG) {
                        long long u = load_idx(uidx, rr, is64);
                        arow = user + (size_t)u * CDIM;
                    } else {
                        arow = text + (size_t)rr * SC;
                    }
                    const float4 va = __ldg(&((const float4*)arow)[kb4 + qd]);
                    const float4 vb = __ldg(&((const float4*)(Wm + (size_t)(j0 + r) * CDIM))[kb4 + qd]);
                    const int k0 = qd * 4;
                    As[k0 + 0][r] = va.x; As[k0 + 1][r] = va.y;
                    As[k0 + 2][r] = va.z; As[k0 + 3][r] = va.w;
                    Bs[k0 + 0][r] = vb.x; Bs[k0 + 1][r] = vb.y;
                    Bs[k0 + 2][r] = vb.z; Bs[k0 + 3][r] = vb.w;
                }
                __syncthreads();

                #pragma unroll 8
                for (int k = 0; k < TK; k++) {
                    const float4 a0 = *(const float4*)&As[k][ty * 8];
                    const float4 a1 = *(const float4*)&As[k][ty * 8 + 4];
                    const float4 b0 = *(const float4*)&Bs[k][tx * 8];
                    const float4 b1 = *(const float4*)&Bs[k][tx * 8 + 4];
                    unsigned long long bp[4];
                    {
                        float2 q0 = make_float2(b0.x, b0.y), q1 = make_float2(b0.z, b0.w);
                        float2 q2 = make_float2(b1.x, b1.y), q3 = make_float2(b1.z, b1.w);
                        bp[0] = *(unsigned long long*)&q0; bp[1] = *(unsigned long long*)&q1;
                        bp[2] = *(unsigned long long*)&q2; bp[3] = *(unsigned long long*)&q3;
                    }
                    const float av[8] = {a0.x, a0.y, a0.z, a0.w, a1.x, a1.y, a1.z, a1.w};
                    #pragma unroll
                    for (int ii = 0; ii < 8; ii++) {
                        const unsigned long long ad = dup2(av[ii]);
                        #pragma unroll
                        for (int jp = 0; jp < 4; jp++) fma2(acc[ii][jp], ad, bp[jp]);
                    }
                }
            }

            // epilogue: reduce sum_j P[r,j]*x[r,j] over tx, atomicAdd
            #pragma unroll
            for (int ii = 0; ii < 8; ii++) {
                const int r = row0 + ty * 8 + ii;
                const int rr = (r < B) ? r : (B - 1);
                const float* xrow;
                if (isG) {
                    long long u = load_idx(uidx, rr, is64);
                    xrow = user + (size_t)u * CDIM;
                } else {
                    xrow = text + (size_t)rr * SC;
                }
                const float4 xa = __ldg(&((const float4*)xrow)[(j0 >> 2) + tx * 2]);
                const float4 xb = __ldg(&((const float4*)xrow)[(j0 >> 2) + tx * 2 + 1]);
                const float2 p0 = unpack2(acc[ii][0]);
                const float2 p1 = unpack2(acc[ii][1]);
                const float2 p2 = unpack2(acc[ii][2]);
                const float2 p3 = unpack2(acc[ii][3]);
                float s = p0.x * xa.x + p0.y * xa.y + p1.x * xa.z + p1.y * xa.w
                        + p2.x * xb.x + p2.y * xb.y + p3.x * xb.z + p3.y * xb.w;
                #pragma unroll
                for (int o = 8; o; o >>= 1) s += __shfl_xor_sync(0xffffffffu, s, o);
                if (tx == 0 && r < B) atomicAdd(&g_quad[isG * QOFF + r], s);
            }

            __threadfence();
            __syncthreads();
            if (tid == 0) *s_item = atomicAdd(&g_ctr, 1u);
            __syncthreads();
            item = *s_item;
        }
        else if (item < NITEMS) {
            // ============ TMA bulk copy chunk: text -> outT ============
            unsigned nG = g + 1; if (nG > NG) nG = NG;
            const unsigned chunk = item - nG;

            if (tid == 0) {
                const int slot = cpyCnt & 1; cpyCnt++;
                *s_item = atomicAdd(&g_ctr, 1u);     // overlap grab with drains
                BULK_WAIT(1);                // slot's previous store retired
                FENCE_ASYNC();               // order any generic smem writes
                const size_t off = (size_t)chunk * BUFB;
                size_t rem = TB - off;
                const uint32_t bytes = (rem < (size_t)BUFB) ? (uint32_t)rem : BUFB;
                const uint32_t mb = mbarBase + slot * 8;
                mbar_expect_tx(mb, bytes);
                bulk_g2s(bufBase + slot * BUFB, (const char*)text + off, bytes, mb);
                const uint32_t par = slot ? ph1 : ph0;
                mbar_wait(mb, par);
                if (slot) ph1 ^= 1u; else ph0 ^= 1u;
                bulk_s2g((char*)outAll + off, bufBase + slot * BUFB, bytes);
                BULK_COMMIT();
            }
            __syncthreads();
            item = *s_item;
        }
        else {
            // ================= finalize item (8 rows) =================
            const unsigned fitem = item - NITEMS;

            if (tid == 0) {
                while (*(volatile unsigned*)&g_passed < (unsigned)gridDim.x)
                    __nanosleep(100);
                while (*(volatile unsigned*)&g_ceDone == 0u)
                    __nanosleep(100);
            }
            __syncthreads();
            __threadfence();

            const int r = (int)fitem * 8 + warp;
            if (r < B) {
                long long u = load_idx(uidx, r, is64);
                const float4* __restrict__ x4  = (const float4*)(text + (size_t)r * SC);
                const float4* __restrict__ g4  = (const float4*)(user + (size_t)u * CDIM);
                const float4* __restrict__ bt4 = (const float4*)bt;
                const float4* __restrict__ bg4 = (const float4*)bg;

                float4 xs[6], gs[6];
                float pxb = 0.f, pgb = 0.f, pxg = 0.f;
                #pragma unroll
                for (int k = 0; k < 6; k++) {
                    xs[k] = x4[lane + 32 * k];
                    gs[k] = g4[lane + 32 * k];
                    const float4 bv = bt4[lane + 32 * k];
                    const float4 gv = bg4[lane + 32 * k];
                    pxb += xs[k].x * bv.x + xs[k].y * bv.y + xs[k].z * bv.z + xs[k].w * bv.w;
                    pgb += gs[k].x * gv.x + gs[k].y * gv.y + gs[k].z * gv.z + gs[k].w * gv.w;
                    pxg += xs[k].x * gs[k].x + xs[k].y * gs[k].y + xs[k].z * gs[k].z + xs[k].w * gs[k].w;
                }
                #pragma unroll
                for (int o = 16; o; o >>= 1) {
                    pxb += __shfl_xor_sync(0xffffffffu, pxb, o);
                    pgb += __shfl_xor_sync(0xffffffffu, pgb, o);
                    pxg += __shfl_xor_sync(0xffffffffu, pxg, o);
                }
                float wa, wc;
                if (lane == 0) {
                    const float a  = g_quad[r] + pxb;          // text_ini . text_tmp
                    const float cq = g_quad[QOFF + r] + pgb;   // graph_tmp . graph_ini
                    const float bq = pxg;                      // graph_ini . text_ini
                    wa = 1.f / (1.f + expf(bq - a));
                    wc = 1.f / (1.f + expf(bq - cq));
                    g_quad[r] = 0.f;                           // reset for replay
                    g_quad[QOFF + r] = 0.f;
                }
                wa = __shfl_sync(0xffffffffu, wa, 0);
                wc = __shfl_sync(0xffffffffu, wc, 0);
                const float wb = 1.f - wa, wd = 1.f - wc;

                float4* __restrict__ oT = (float4*)(outAll + (size_t)r * SC);
                float4* __restrict__ oU = (float4*)(outAll + text_n + (size_t)u * CDIM);
                #pragma unroll
                for (int k = 0; k < 6; k++) {
                    float4 to, uo;
                    to.x = wa * xs[k].x + wb * gs[k].x;  uo.x = wc * gs[k].x + wd * xs[k].x;
                    to.y = wa * xs[k].y + wb * gs[k].y;  uo.y = wc * gs[k].y + wd * xs[k].y;
                    to.z = wa * xs[k].z + wb * gs[k].z;  uo.z = wc * gs[k].z + wd * xs[k].z;
                    to.w = wa * xs[k].w + wb * gs[k].w;  uo.w = wc * gs[k].w + wd * xs[k].w;
                    oT[lane + 32 * k] = to;
                    oU[lane + 32 * k] = uo;
                }
            }

            __syncthreads();
            if (tid == 0) *s_item = atomicAdd(&g_ctr, 1u);
            __syncthreads();
            item = *s_item;
        }
    }

    // exit: last block resets queue state for the next graph replay
    __syncthreads();
    if (tid == 0) {
        const unsigned tt = atomicAdd(&g_exit, 1u);
        if (tt == gridDim.x - 1) {
            g_ctr = 0u; g_passed = 0u; g_ceDone = 0u;
            __threadfence();
            g_exit = 0u;
        }
    }
}

// ---------------------------------------------------------------------------
extern "C" void kernel_launch(void* const* d_in, const int* in_sizes, int n_in,
                              void* d_out, int out_size)
{
    static cudaStream_t s2 = 0, s3 = 0;
    static cudaEvent_t evA = 0, evC = 0, evD = 0;
    static bool inited = false;
    if (!inited) {
        cudaStreamCreateWithFlags(&s2, cudaStreamNonBlocking);
        cudaStreamCreateWithFlags(&s3, cudaStreamNonBlocking);
        cudaEventCreateWithFlags(&evA, cudaEventDisableTiming);
        cudaEventCreateWithFlags(&evC, cudaEventDisableTiming);
        cudaEventCreateWithFlags(&evD, cudaEventDisableTiming);
        cudaFuncSetAttribute(mega, cudaFuncAttributeMaxDynamicSharedMemorySize,
                             SMEM_TOTAL);
        inited = true;
    }

    const float* text = (const float*)d_in[0];
    const float* user = (const float*)d_in[1];
    const void*  uidx = d_in[2];
    const float* Wt   = (const float*)d_in[3];
    const float* bt   = (const float*)d_in[4];
    const float* Wg   = (const float*)d_in[5];
    const float* bg   = (const float*)d_in[6];

    const long long text_n = in_sizes[0];
    const long long user_n = in_sizes[1];
    const int B = in_sizes[2];
    const long long SC = text_n / (long long)B;   // S*C
    const long long user_rows = user_n / CDIM;

    float* outAll = (float*)d_out;

    const unsigned perM = (unsigned)((B / TM) * JTILES);   // 96
    const unsigned NG = 2 * perM;                           // 192
    const size_t TB = (size_t)text_n * 4;                   // text bytes
    const unsigned NCHUNK = (unsigned)((TB + BUFB - 1) / BUFB);
    const unsigned NITEMS = NG + NCHUNK;
    unsigned P = (NITEMS / 2) / NG;                         // GEMM in 1st half
    if (P < 1) P = 1;
    const unsigned NFIN = (unsigned)((B + 7) / 8);
    const unsigned TOTAL = NITEMS + NFIN;

    // fork: copy engines handle the whole user tensor -> outU (two halves on
    // two streams), then ceFlag on s2 signals completion to mega's finalize.
    const size_t half_elems = ((size_t)user_n / 2) & ~((size_t)3);
    cudaEventRecord(evA, 0);
    cudaStreamWaitEvent(s2, evA, 0);
    cudaStreamWaitEvent(s3, evA, 0);
    cudaMemcpyAsync(outAll + text_n, user, half_elems * sizeof(float),
                    cudaMemcpyDeviceToDevice, s2);
    cudaMemcpyAsync(outAll + text_n + half_elems, user + half_elems,
                    ((size_t)user_n - half_elems) * sizeof(float),
                    cudaMemcpyDeviceToDevice, s3);
    cudaEventRecord(evC, s3);
    cudaStreamWaitEvent(s2, evC, 0);     // s2 now trails BOTH memcpys
    ceFlag<<<1, 1, 0, s2>>>();           // runs in a reserved SM slot
    cudaEventRecord(evD, s2);

    mega<<<NBLOCKS, NTHREADS, SMEM_TOTAL>>>(text, user, uidx, Wt, bt, Wg, bg,
                                            outAll, B, SC, text_n, user_rows,
                                            NG, P, NITEMS, TOTAL);

    // join the fork back into the default stream (capture-legal leaf)
    cudaStreamWaitEvent(0, evD, 0);
}

// round 15
// speedup vs baseline: 1.1335x; 1.1335x over previous
#include <cuda_runtime.h>
#include <cstdint>

#define CDIM  768
#define CDIM4 192           // CDIM/4
#define NTHREADS 256
#define NBLOCKS  304        // 152 SMs * 2 blocks
#define TM 128
#define TN 128
#define TK 32
#define KTILES (CDIM / TK)  // 24
#define JTILES (CDIM / TN)  // 6
#define QOFF 4096           // scratch stride (max B = 4096)
#define TMP (TM + 4)        // padded smem row
#define BUFB 49152          // 48 KB TMA staging buffer
#define SMEM_HDR 1024
#define SMEM_TOTAL (SMEM_HDR + 2 * BUFB)   // 99328 B dynamic smem

// quadratic-form scratch: [0,B) text, [QOFF,QOFF+B) graph. Zero at entry:
// zero-initialized at load; re-zeroed by finalize items each replay.
__device__ float g_quad[2 * QOFF];
__device__ float g_ubuf[QOFF * CDIM];   // blended user rows (finalize -> fixup)
__device__ unsigned g_ctr;              // work-queue head
__device__ unsigned g_passed;           // blocks past all pre-finalize work
__device__ unsigned g_exit;             // exited blocks

// user_index may be int64 (declared) or int32 (JAX x64-off default).
__device__ __forceinline__ int detect_is64(const void* uptr, int B, long long nrows) {
    if (B < 2) return 1;
    long long v = ((const long long*)uptr)[B / 2 - 1];
    return (v >= 0 && v < nrows) ? 1 : 0;
}
__device__ __forceinline__ long long load_idx(const void* uptr, int i, int is64) {
    if (is64) return ((const long long*)uptr)[i];
    return (long long)((const int*)uptr)[i];
}

// ---- packed fp32x2 helpers (SASS FFMA2; ptxas never auto-fuses) ----
__device__ __forceinline__ unsigned long long dup2(float a) {
    unsigned long long d; unsigned ai = __float_as_uint(a);
    asm("mov.b64 %0, {%1, %1};" : "=l"(d) : "r"(ai));
    return d;
}
__device__ __forceinline__ void fma2(unsigned long long& acc,
                                     unsigned long long a, unsigned long long b) {
    asm("fma.rn.f32x2 %0, %1, %2, %0;" : "+l"(acc) : "l"(a), "l"(b));
}
__device__ __forceinline__ float2 unpack2(unsigned long long v) {
    float2 r;
    asm("mov.b64 {%0, %1}, %2;" : "=f"(r.x), "=f"(r.y) : "l"(v));
    return r;
}

// ---- TMA bulk + mbarrier helpers ----
__device__ __forceinline__ uint32_t smem_u32(const void* p) {
    uint32_t a;
    asm("{ .reg .u64 t; cvta.to.shared.u64 t, %1; cvt.u32.u64 %0, t; }"
        : "=r"(a) : "l"(p));
    return a;
}
__device__ __forceinline__ void mbar_init(uint32_t mb, uint32_t cnt) {
    asm volatile("mbarrier.init.shared.b64 [%0], %1;" :: "r"(mb), "r"(cnt) : "memory");
}
__device__ __forceinline__ void mbar_expect_tx(uint32_t mb, uint32_t bytes) {
    asm volatile("mbarrier.arrive.expect_tx.shared.b64 _, [%0], %1;"
                 :: "r"(mb), "r"(bytes) : "memory");
}
__device__ __forceinline__ void mbar_wait(uint32_t mb, uint32_t parity) {
    asm volatile(
        "{\n\t"
        ".reg .pred P1;\n\t"
        "WAIT_LOOP_%=:\n\t"
        "mbarrier.try_wait.parity.acquire.cta.shared::cta.b64 P1, [%0], %1, 0x989680;\n\t"
        "@P1 bra.uni WAIT_DONE_%=;\n\t"
        "bra.uni WAIT_LOOP_%=;\n\t"
        "WAIT_DONE_%=:\n\t"
        "}"
        :: "r"(mb), "r"(parity) : "memory");
}
__device__ __forceinline__ void bulk_g2s(uint32_t dst, const void* src,
                                         uint32_t bytes, uint32_t mb) {
    asm volatile(
        "cp.async.bulk.shared::cta.global.mbarrier::complete_tx::bytes "
        "[%0], [%1], %2, [%3];"
        :: "r"(dst), "l"(src), "r"(bytes), "r"(mb) : "memory");
}
__device__ __forceinline__ void bulk_s2g(void* dst, uint32_t src, uint32_t bytes) {
    asm volatile(
        "cp.async.bulk.global.shared::cta.bulk_group [%0], [%1], %2;"
        :: "l"(dst), "r"(src), "r"(bytes) : "memory");
}
#define BULK_COMMIT()  asm volatile("cp.async.bulk.commit_group;" ::: "memory")
#define BULK_WAIT(n)   asm volatile("cp.async.bulk.wait_group " #n ";" ::: "memory")
#define FENCE_ASYNC()  asm volatile("fence.proxy.async.shared::cta;" ::: "memory")

// ---------------------------------------------------------------------------
// Mega kernel. Queue items:
//   [0, NITEMS): g=item/P; GEMM tile if item%P==0 && g<NG; else a 48 KB TMA
//                bulk copy chunk of text -> outT (double-buffered in smem).
//   [NITEMS, TOTAL): finalize rows — wait g_passed == gridDim.x (each block
//                signals passed only AFTER cp.async.bulk.wait_group 0, so all
//                async stores are complete before finalize overwrites).
// CE concurrently copies all of user -> outU; blended user rows -> g_ubuf.
// ---------------------------------------------------------------------------
__global__ void __launch_bounds__(NTHREADS, 2)
mega(const float* __restrict__ text,
     const float* __restrict__ user,
     const void*  __restrict__ uidx,
     const float* __restrict__ Wt,
     const float* __restrict__ bt,
     const float* __restrict__ Wg,
     const float* __restrict__ bg,
     float* __restrict__ outAll,           // outT (text_n) then outU (user_n)
     int B, long long SC, long long text_n, long long user_rows,
     unsigned NG, unsigned P, unsigned NITEMS, unsigned TOTAL)
{
    extern __shared__ char smdyn[];
    unsigned* s_item = (unsigned*)smdyn;
    const uint32_t mbarBase = smem_u32(smdyn + 64);
    const uint32_t bufBase  = smem_u32(smdyn + SMEM_HDR);
    float (*As)[TMP] = (float(*)[TMP])(smdyn + SMEM_HDR);
    float (*Bs)[TMP] = (float(*)[TMP])(smdyn + SMEM_HDR + TK * TMP * 4);

    const int tid  = threadIdx.x;
    const int warp = tid >> 5;
    const int lane = tid & 31;
    const int tx   = tid & 15;    // j-fragment index
    const int ty   = tid >> 4;    // row-fragment index

    const size_t TB = (size_t)text_n * 4;   // text bytes
    const unsigned perM = NG >> 1;

    if (tid == 0) {
        mbar_init(mbarBase + 0, 1);
        mbar_init(mbarBase + 8, 1);
        asm volatile("fence.mbarrier_init.release.cluster;" ::: "memory");
        *s_item = atomicAdd(&g_ctr, 1u);
    }
    __syncthreads();
    unsigned item = *s_item;
    bool passed = false;
    unsigned ph0 = 0, ph1 = 0;    // mbarrier phases (tid0 only)
    int cpyCnt = 0;               // per-block copy-slot alternation

    const int is64 = detect_is64(uidx, B, user_rows);

    for (;;) {
        if (!passed && item >= NITEMS) {
            if (tid == 0) {
                BULK_WAIT(0);                // all async stores retired
                __threadfence();
                atomicAdd(&g_passed, 1u);
            }
            passed = true;
        }
        if (item >= TOTAL) break;

        const unsigned g = item / P;
        const bool isGemm = (item < NITEMS) && (item - g * P == 0u) && (g < NG);

        if (isGemm) {
            // ================= GEMM bilinear-form tile =================
            if (tid == 0) BULK_WAIT(0);      // smem buffers free for reuse
            __syncthreads();

            const int isG = (g >= perM) ? 1 : 0;
            const int qq  = isG ? (int)(g - perM) : (int)g;
            const int mt  = qq / JTILES;
            const int jt  = qq % JTILES;
            const int row0 = mt * TM;
            const int j0   = jt * TN;
            const float* __restrict__ Wm = isG ? Wg : Wt;

            unsigned long long acc[8][4];
            #pragma unroll
            for (int i = 0; i < 8; i++)
                #pragma unroll
                for (int j = 0; j < 4; j++) acc[i][j] = 0ull;

            for (int kt = 0; kt < KTILES; kt++) {
                const int kb4 = kt * (TK / 4);
                __syncthreads();
                #pragma unroll
                for (int it = 0; it < 4; it++) {
                    const int f  = it * NTHREADS + tid;
                    const int r  = f >> 3;
                    const int qd = f & 7;
                    int rr = row0 + r; if (rr >= B) rr = B - 1;
                    const float* arow;
                    if (isG) {
                        long long u = load_idx(uidx, rr, is64);
                        arow = user + (size_t)u * CDIM;
                    } else {
                        arow = text + (size_t)rr * SC;
                    }
                    const float4 va = __ldg(&((const float4*)arow)[kb4 + qd]);
                    const float4 vb = __ldg(&((const float4*)(Wm + (size_t)(j0 + r) * CDIM))[kb4 + qd]);
                    const int k0 = qd * 4;
                    As[k0 + 0][r] = va.x; As[k0 + 1][r] = va.y;
                    As[k0 + 2][r] = va.z; As[k0 + 3][r] = va.w;
                    Bs[k0 + 0][r] = vb.x; Bs[k0 + 1][r] = vb.y;
                    Bs[k0 + 2][r] = vb.z; Bs[k0 + 3][r] = vb.w;
                }
                __syncthreads();

                #pragma unroll 8
                for (int k = 0; k < TK; k++) {
                    const float4 a0 = *(const float4*)&As[k][ty * 8];
                    const float4 a1 = *(const float4*)&As[k][ty * 8 + 4];
                    const float4 b0 = *(const float4*)&Bs[k][tx * 8];
                    const float4 b1 = *(const float4*)&Bs[k][tx * 8 + 4];
                    unsigned long long bp[4];
                    {
                        float2 q0 = make_float2(b0.x, b0.y), q1 = make_float2(b0.z, b0.w);
                        float2 q2 = make_float2(b1.x, b1.y), q3 = make_float2(b1.z, b1.w);
                        bp[0] = *(unsigned long long*)&q0; bp[1] = *(unsigned long long*)&q1;
                        bp[2] = *(unsigned long long*)&q2; bp[3] = *(unsigned long long*)&q3;
                    }
                    const float av[8] = {a0.x, a0.y, a0.z, a0.w, a1.x, a1.y, a1.z, a1.w};
                    #pragma unroll
                    for (int ii = 0; ii < 8; ii++) {
                        const unsigned long long ad = dup2(av[ii]);
                        #pragma unroll
                        for (int jp = 0; jp < 4; jp++) fma2(acc[ii][jp], ad, bp[jp]);
                    }
                }
            }

            // epilogue: reduce sum_j P[r,j]*x[r,j] over tx, atomicAdd
            #pragma unroll
            for (int ii = 0; ii < 8; ii++) {
                const int r = row0 + ty * 8 + ii;
                const int rr = (r < B) ? r : (B - 1);
                const float* xrow;
                if (isG) {
                    long long u = load_idx(uidx, rr, is64);
                    xrow = user + (size_t)u * CDIM;
                } else {
                    xrow = text + (size_t)rr * SC;
                }
                const float4 xa = __ldg(&((const float4*)xrow)[(j0 >> 2) + tx * 2]);
                const float4 xb = __ldg(&((const float4*)xrow)[(j0 >> 2) + tx * 2 + 1]);
                const float2 p0 = unpack2(acc[ii][0]);
                const float2 p1 = unpack2(acc[ii][1]);
                const float2 p2 = unpack2(acc[ii][2]);
                const float2 p3 = unpack2(acc[ii][3]);
                float s = p0.x * xa.x + p0.y * xa.y + p1.x * xa.z + p1.y * xa.w
                        + p2.x * xb.x + p2.y * xb.y + p3.x * xb.z + p3.y * xb.w;
                #pragma unroll
                for (int o = 8; o; o >>= 1) s += __shfl_xor_sync(0xffffffffu, s, o);
                if (tx == 0 && r < B) atomicAdd(&g_quad[isG * QOFF + r], s);
            }

            __threadfence();
            __syncthreads();
            if (tid == 0) *s_item = atomicAdd(&g_ctr, 1u);
            __syncthreads();
            item = *s_item;
        }
        else if (item < NITEMS) {
            // ============ TMA bulk copy chunk: text -> outT ============
            unsigned nG = g + 1; if (nG > NG) nG = NG;
            const unsigned chunk = item - nG;

            if (tid == 0) {
                const int slot = cpyCnt & 1; cpyCnt++;
                *s_item = atomicAdd(&g_ctr, 1u);     // overlap grab with drains
                BULK_WAIT(1);                // slot's previous store retired
                FENCE_ASYNC();               // order any generic smem writes
                const size_t off = (size_t)chunk * BUFB;
                size_t rem = TB - off;
                const uint32_t bytes = (rem < (size_t)BUFB) ? (uint32_t)rem : BUFB;
                const uint32_t mb = mbarBase + slot * 8;
                mbar_expect_tx(mb, bytes);
                bulk_g2s(bufBase + slot * BUFB, (const char*)text + off, bytes, mb);
                const uint32_t par = slot ? ph1 : ph0;
                mbar_wait(mb, par);
                if (slot) ph1 ^= 1u; else ph0 ^= 1u;
                bulk_s2g((char*)outAll + off, bufBase + slot * BUFB, bytes);
                BULK_COMMIT();
            }
            __syncthreads();
            item = *s_item;
        }
        else {
            // ================= finalize item (8 rows) =================
            const unsigned fitem = item - NITEMS;

            if (tid == 0) {
                while (*(volatile unsigned*)&g_passed < (unsigned)gridDim.x)
                    __nanosleep(100);
            }
            __syncthreads();
            __threadfence();

            const int r = (int)fitem * 8 + warp;
            if (r < B) {
                long long u = load_idx(uidx, r, is64);
                const float4* __restrict__ x4  = (const float4*)(text + (size_t)r * SC);
                const float4* __restrict__ g4  = (const float4*)(user + (size_t)u * CDIM);
                const float4* __restrict__ bt4 = (const float4*)bt;
                const float4* __restrict__ bg4 = (const float4*)bg;

                float4 xs[6], gs[6];
                float pxb = 0.f, pgb = 0.f, pxg = 0.f;
                #pragma unroll
                for (int k = 0; k < 6; k++) {
                    xs[k] = x4[lane + 32 * k];
                    gs[k] = g4[lane + 32 * k];
                    const float4 bv = bt4[lane + 32 * k];
                    const float4 gv = bg4[lane + 32 * k];
                    pxb += xs[k].x * bv.x + xs[k].y * bv.y + xs[k].z * bv.z + xs[k].w * bv.w;
                    pgb += gs[k].x * gv.x + gs[k].y * gv.y + gs[k].z * gv.z + gs[k].w * gv.w;
                    pxg += xs[k].x * gs[k].x + xs[k].y * gs[k].y + xs[k].z * gs[k].z + xs[k].w * gs[k].w;
                }
                #pragma unroll
                for (int o = 16; o; o >>= 1) {
                    pxb += __shfl_xor_sync(0xffffffffu, pxb, o);
                    pgb += __shfl_xor_sync(0xffffffffu, pgb, o);
                    pxg += __shfl_xor_sync(0xffffffffu, pxg, o);
                }
                float wa, wc;
                if (lane == 0) {
                    const float a  = g_quad[r] + pxb;          // text_ini . text_tmp
                    const float cq = g_quad[QOFF + r] + pgb;   // graph_tmp . graph_ini
                    const float bq = pxg;                      // graph_ini . text_ini
                    wa = 1.f / (1.f + expf(bq - a));
                    wc = 1.f / (1.f + expf(bq - cq));
                    g_quad[r] = 0.f;                           // reset for replay
                    g_quad[QOFF + r] = 0.f;
                }
                wa = __shfl_sync(0xffffffffu, wa, 0);
                wc = __shfl_sync(0xffffffffu, wc, 0);
                const float wb = 1.f - wa, wd = 1.f - wc;

                float4* __restrict__ oT = (float4*)(outAll + (size_t)r * SC);
                float4* __restrict__ oU = (float4*)(g_ubuf + (size_t)r * CDIM);
                #pragma unroll
                for (int k = 0; k < 6; k++) {
                    float4 to, uo;
                    to.x = wa * xs[k].x + wb * gs[k].x;  uo.x = wc * gs[k].x + wd * xs[k].x;
                    to.y = wa * xs[k].y + wb * gs[k].y;  uo.y = wc * gs[k].y + wd * xs[k].y;
                    to.z = wa * xs[k].z + wb * gs[k].z;  uo.z = wc * gs[k].z + wd * xs[k].z;
                    to.w = wa * xs[k].w + wb * gs[k].w;  uo.w = wc * gs[k].w + wd * xs[k].w;
                    oT[lane + 32 * k] = to;
                    oU[lane + 32 * k] = uo;
                }
            }

            __syncthreads();
            if (tid == 0) *s_item = atomicAdd(&g_ctr, 1u);
            __syncthreads();
            item = *s_item;
        }
    }

    // exit: last block resets queue state for the next graph replay
    __syncthreads();
    if (tid == 0) {
        const unsigned tt = atomicAdd(&g_exit, 1u);
        if (tt == gridDim.x - 1) {
            g_ctr = 0u; g_passed = 0u;
            __threadfence();
            g_exit = 0u;
        }
    }
}

// ---------------------------------------------------------------------------
// Fixup: scatter precomputed blended user rows (g_ubuf, L2-hot) into outU.
// Runs after mega and after the CE memcpy join (stream-ordered).
// ---------------------------------------------------------------------------
__global__ void __launch_bounds__(NTHREADS)
fixup(const void* __restrict__ uidx,
      float* __restrict__ outAll,
      int B, long long text_n, long long user_rows)
{
    const int warp = threadIdx.x >> 5;
    const int lane = threadIdx.x & 31;
    const int r = blockIdx.x * 8 + warp;
    if (r >= B) return;
    const int is64 = detect_is64(uidx, B, user_rows);
    const long long u = load_idx(uidx, r, is64);

    const float4* __restrict__ src = (const float4*)(g_ubuf + (size_t)r * CDIM);
    float4* __restrict__ dst = (float4*)(outAll + text_n + (size_t)u * CDIM);
    #pragma unroll
    for (int k = 0; k < 6; k++)
        dst[lane + 32 * k] = src[lane + 32 * k];
}

// ---------------------------------------------------------------------------
extern "C" void kernel_launch(void* const* d_in, const int* in_sizes, int n_in,
                              void* d_out, int out_size)
{
    static cudaStream_t s2 = 0, s3 = 0;
    static cudaEvent_t evA = 0, evB = 0, evC = 0;
    static bool inited = false;
    if (!inited) {
        cudaStreamCreateWithFlags(&s2, cudaStreamNonBlocking);
        cudaStreamCreateWithFlags(&s3, cudaStreamNonBlocking);
        cudaEventCreateWithFlags(&evA, cudaEventDisableTiming);
        cudaEventCreateWithFlags(&evB, cudaEventDisableTiming);
        cudaEventCreateWithFlags(&evC, cudaEventDisableTiming);
        cudaFuncSetAttribute(mega, cudaFuncAttributeMaxDynamicSharedMemorySize,
                             SMEM_TOTAL);
        inited = true;
    }

    const float* text = (const float*)d_in[0];
    const float* user = (const float*)d_in[1];
    const void*  uidx = d_in[2];
    const float* Wt   = (const float*)d_in[3];
    const float* bt   = (const float*)d_in[4];
    const float* Wg   = (const float*)d_in[5];
    const float* bg   = (const float*)d_in[6];

    const long long text_n = in_sizes[0];
    const long long user_n = in_sizes[1];
    const int B = in_sizes[2];
    const long long SC = text_n / (long long)B;   // S*C
    const long long user_rows = user_n / CDIM;

    float* outAll = (float*)d_out;

    const unsigned perM = (unsigned)((B / TM) * JTILES);   // 96
    const unsigned NG = 2 * perM;                           // 192
    const size_t TB = (size_t)text_n * 4;                   // text bytes
    const unsigned NCHUNK = (unsigned)((TB + BUFB - 1) / BUFB);
    const unsigned NITEMS = NG + NCHUNK;
    unsigned P = (NITEMS / 2) / NG;                         // GEMM in 1st half
    if (P < 1) P = 1;
    const unsigned NFIN = (unsigned)((B + 7) / 8);
    const unsigned TOTAL = NITEMS + NFIN;

    // fork: copy engines handle the whole user tensor -> outU, two halves on
    // two streams (parallel engines if available; harmless if serialized)
    const size_t half_elems = ((size_t)user_n / 2) & ~((size_t)3);
    cudaEventRecord(evA, 0);
    cudaStreamWaitEvent(s2, evA, 0);
    cudaStreamWaitEvent(s3, evA, 0);
    cudaMemcpyAsync(outAll + text_n, user, half_elems * sizeof(float),
                    cudaMemcpyDeviceToDevice, s2);
    cudaMemcpyAsync(outAll + text_n + half_elems, user + half_elems,
                    ((size_t)user_n - half_elems) * sizeof(float),
                    cudaMemcpyDeviceToDevice, s3);
    cudaEventRecord(evB, s2);
    cudaEventRecord(evC, s3);

    mega<<<NBLOCKS, NTHREADS, SMEM_TOTAL>>>(text, user, uidx, Wt, bt, Wg, bg,
                                            outAll, B, SC, text_n, user_rows,
                                            NG, P, NITEMS, TOTAL);

    // join CEs, then scatter the blended user rows over the CE-copied data
    cudaStreamWaitEvent(0, evB, 0);
    cudaStreamWaitEvent(0, evC, 0);
    fixup<<<(B + 7) / 8, NTHREADS>>>(uidx, outAll, B, text_n, user_rows);
}